// round 5
// baseline (speedup 1.0000x reference)
#include <cuda_runtime.h>
#include <math.h>
#include <stdint.h>

// ---------------------------------------------------------------------------
// Problem constants
// ---------------------------------------------------------------------------
#define T_ROWS 65536      // B*C*S tokens (1024 * 64)
#define DM     256
#define DKV    128

// scratch layout (float offsets) inside one big __device__ buffer
#define OFF_NORMA 0UL          // 65536*256
#define OFF_NORMB 16777216UL   // 65536*256
#define OFF_Q     33554432UL   // 2 * 65536*256
#define OFF_K     67108864UL   // 2 * 65536*128
#define OFF_V     83886080UL   // 2 * 65536*128
#define OFF_AO    100663296UL  // 2 * 65536*256
#define OFF_WQ    134217728UL  // 2 * 256*256
#define OFF_WK    134348800UL  // 2 * 256*128
#define OFF_WV    134414336UL  // 2 * 256*128
#define OFF_BQ    134479872UL  // 2 * 256
#define OFF_BK    134480384UL  // 2 * 128
#define OFF_BV    134480640UL  // 2 * 128
#define BUF_TOTAL 134480896UL

__device__ float g_buf[BUF_TOTAL];

// ---------------------------------------------------------------------------
// tf32 mma.sync helpers
// ---------------------------------------------------------------------------
__device__ __forceinline__ unsigned f2tf(float x) {
    unsigned r;
    asm("cvt.rna.tf32.f32 %0, %1;" : "=r"(r) : "f"(x));
    return r;
}

__device__ __forceinline__ void mma_tf32(float* c,
                                         unsigned a0, unsigned a1, unsigned a2, unsigned a3,
                                         unsigned b0, unsigned b1) {
    asm("mma.sync.aligned.m16n8k8.row.col.f32.tf32.tf32.f32 "
        "{%0,%1,%2,%3},{%4,%5,%6,%7},{%8,%9},{%0,%1,%2,%3};"
        : "+f"(c[0]), "+f"(c[1]), "+f"(c[2]), "+f"(c[3])
        : "r"(a0), "r"(a1), "r"(a2), "r"(a3), "r"(b0), "r"(b1));
}

// ---------------------------------------------------------------------------
// Prep kernels: fold LN affine into projection weights
//   LN(x) @ W + bias = norm(x) @ (diag(g) W) + (b_ln @ W + bias)
// ---------------------------------------------------------------------------
__global__ void scale_w_kernel(const float* __restrict__ W, const float* __restrict__ g,
                               float* __restrict__ Wout, int N) {
    int idx = blockIdx.x * blockDim.x + threadIdx.x;
    if (idx < 256 * N) {
        int d = idx / N;
        Wout[idx] = W[idx] * g[d];
    }
}

__global__ void bias_fold_kernel(const float* __restrict__ W, const float* __restrict__ b_ln,
                                 const float* __restrict__ b_lin, float* __restrict__ bout, int N) {
    int e = blockIdx.x * blockDim.x + threadIdx.x;
    if (e < N) {
        float s = b_lin[e];
        for (int d = 0; d < 256; d++) s += b_ln[d] * W[d * N + e];
        bout[e] = s;
    }
}

// ---------------------------------------------------------------------------
// LayerNorm (normalization only; affine folded into weights).
// Input layout (B,S,C,D); output layout (bc, s, d) row-major, rows = bc*64+s.
// One warp per row; 8 warps / block.
// ---------------------------------------------------------------------------
__global__ void __launch_bounds__(256) ln_kernel(const float* __restrict__ x_spec,
                                                 const float* __restrict__ x_spat,
                                                 float* __restrict__ normA,
                                                 float* __restrict__ normB) {
    int gw = blockIdx.x * 8 + (threadIdx.x >> 5);
    int lane = threadIdx.x & 31;
    const float* src;
    float* dst;
    int r;
    if (gw < T_ROWS) { src = x_spec; dst = normA; r = gw; }
    else             { src = x_spat; dst = normB; r = gw - T_ROWS; }
    int bc = r >> 6, s = r & 63;
    int b = bc >> 7, c = bc & 127;
    const float* row = src + ((size_t)((b * 64 + s) * 128 + c)) * 256;
    float v[8];
    float sum = 0.f, sq = 0.f;
#pragma unroll
    for (int t = 0; t < 8; t++) {
        float x = row[lane + 32 * t];
        v[t] = x; sum += x; sq += x * x;
    }
#pragma unroll
    for (int o = 16; o > 0; o >>= 1) {
        sum += __shfl_xor_sync(0xffffffffu, sum, o);
        sq  += __shfl_xor_sync(0xffffffffu, sq, o);
    }
    float mu  = sum * (1.f / 256.f);
    float var = sq * (1.f / 256.f) - mu * mu;
    float rs  = rsqrtf(var + 1e-5f);
    float* orow = dst + (size_t)r * 256;
#pragma unroll
    for (int t = 0; t < 8; t++) orow[lane + 32 * t] = (v[t] - mu) * rs;
}

// ---------------------------------------------------------------------------
// tf32 GEMM: C[M=65536, N] = A[M,256] @ W[256,N] + bias
// mode 0: plain store row-major.
// mode 1: O-proj epilogue: out[(b,s,c,:)] = x + sigmoid(gate)*(C+bias)  (transpose back)
// Tile: BM=128, BN=64, BK=32. 8 warps (4m x 2n), warp tile 32x32.
// ---------------------------------------------------------------------------
#define GBM 128
#define GBN 64
#define GBK 32
#define GBKP 36
#define GBNP 68

__global__ void __launch_bounds__(256) gemm_kernel(
    const float* __restrict__ A, const float* __restrict__ W, const float* __restrict__ bias,
    float* __restrict__ out, int N, int mode,
    const float* __restrict__ xres, const float* __restrict__ gate) {
    __shared__ float As[GBM][GBKP];
    __shared__ float Bs[GBK][GBNP];
    int tid = threadIdx.x;
    int wid = tid >> 5, lane = tid & 31;
    int gid = lane >> 2, ctid = lane & 3;
    int wm = (wid & 3) * 32;
    int wn = (wid >> 2) * 32;
    int rowBase = blockIdx.x * GBM;
    int colBase = blockIdx.y * GBN;

    float acc[2][4][4];
#pragma unroll
    for (int mt = 0; mt < 2; mt++)
#pragma unroll
        for (int nt = 0; nt < 4; nt++)
#pragma unroll
            for (int j = 0; j < 4; j++) acc[mt][nt][j] = 0.f;

    for (int k0 = 0; k0 < 256; k0 += GBK) {
        // load A tile 128x32 (1024 float4)
#pragma unroll
        for (int it = 0; it < 4; it++) {
            int f4 = tid + 256 * it;
            int r = f4 >> 3, c4 = f4 & 7;
            float4 v = *(const float4*)(A + (size_t)(rowBase + r) * 256 + k0 + c4 * 4);
            *(float4*)&As[r][c4 * 4] = v;
        }
        // load B tile 32x64 (512 float4)
#pragma unroll
        for (int it = 0; it < 2; it++) {
            int f4 = tid + 256 * it;
            int r = f4 >> 4, c4 = f4 & 15;
            float4 v = *(const float4*)(W + (size_t)(k0 + r) * N + colBase + c4 * 4);
            *(float4*)&Bs[r][c4 * 4] = v;
        }
        __syncthreads();
#pragma unroll
        for (int kt = 0; kt < 4; kt++) {
            unsigned a[2][4], b[4][2];
#pragma unroll
            for (int mt = 0; mt < 2; mt++) {
                int r = wm + 16 * mt + gid;
                a[mt][0] = f2tf(As[r][8 * kt + ctid]);
                a[mt][1] = f2tf(As[r + 8][8 * kt + ctid]);
                a[mt][2] = f2tf(As[r][8 * kt + ctid + 4]);
                a[mt][3] = f2tf(As[r + 8][8 * kt + ctid + 4]);
            }
#pragma unroll
            for (int nt = 0; nt < 4; nt++) {
                int cc = wn + 8 * nt + gid;
                b[nt][0] = f2tf(Bs[8 * kt + ctid][cc]);
                b[nt][1] = f2tf(Bs[8 * kt + ctid + 4][cc]);
            }
#pragma unroll
            for (int mt = 0; mt < 2; mt++)
#pragma unroll
                for (int nt = 0; nt < 4; nt++)
                    mma_tf32(acc[mt][nt], a[mt][0], a[mt][1], a[mt][2], a[mt][3],
                             b[nt][0], b[nt][1]);
        }
        __syncthreads();
    }

    float gs = 0.f;
    if (mode == 1) gs = 1.f / (1.f + __expf(-gate[0]));

#pragma unroll
    for (int mt = 0; mt < 2; mt++) {
#pragma unroll
        for (int nt = 0; nt < 4; nt++) {
            int e = colBase + wn + 8 * nt + 2 * ctid;
            float b0 = bias[e], b1 = bias[e + 1];
            int r0 = rowBase + wm + 16 * mt + gid;
            float v00 = acc[mt][nt][0] + b0, v01 = acc[mt][nt][1] + b1;
            float v10 = acc[mt][nt][2] + b0, v11 = acc[mt][nt][3] + b1;
            if (mode == 0) {
                *(float2*)(out + (size_t)r0 * N + e) = make_float2(v00, v01);
                *(float2*)(out + (size_t)(r0 + 8) * N + e) = make_float2(v10, v11);
            } else {
#pragma unroll
                for (int rr = 0; rr < 2; rr++) {
                    int r = r0 + 8 * rr;
                    int bc = r >> 6, s = r & 63;
                    int b = bc >> 7, c = bc & 127;
                    size_t idx = ((size_t)((b * 64 + s) * 128 + c)) * 256 + e;
                    float2 xv = *(const float2*)(xres + idx);
                    float va = (rr == 0) ? v00 : v10;
                    float vb = (rr == 0) ? v01 : v11;
                    *(float2*)(out + idx) = make_float2(xv.x + gs * va, xv.y + gs * vb);
                }
            }
        }
    }
}

// ---------------------------------------------------------------------------
// Attention: block = (bc, module), warp = head (8 heads). GQA: head h -> kv h/2.
// S = (Q*scale) @ K^T  (tf32 mma), softmax in SMEM (unnormalized exp + 1/rowsum),
// O = P @ V (tf32 mma), scaled by 1/rowsum at the end.
// SMEM: Ks[4][64][36], Vs[4][64][36], per-warp workspace Ws[64][68]
// (cols 0..63 data, col 64 holds 1/rowsum).
// ---------------------------------------------------------------------------
#define ATT_KS_F   (4 * 64 * 36)
#define ATT_WARP_F (64 * 68)
#define ATT_SMEM_F (2 * ATT_KS_F + 8 * ATT_WARP_F)
#define ATT_SMEM_B (ATT_SMEM_F * 4)

__global__ void __launch_bounds__(256) attn_kernel(const float* __restrict__ Qb,
                                                   const float* __restrict__ Kb,
                                                   const float* __restrict__ Vb,
                                                   float* __restrict__ AOb) {
    extern __shared__ float sm[];
    float* Ks = sm;
    float* Vs = sm + ATT_KS_F;
    float* Wsall = sm + 2 * ATT_KS_F;

    int m = blockIdx.y;
    int bc = blockIdx.x;
    const float* Q = Qb + (size_t)m * T_ROWS * 256;
    const float* K = Kb + (size_t)m * T_ROWS * 128;
    const float* V = Vb + (size_t)m * T_ROWS * 128;
    float* AO = AOb + (size_t)m * T_ROWS * 256;

    int tid = threadIdx.x, wid = tid >> 5, lane = tid & 31;
    int gid = lane >> 2, ctid = lane & 3;

    // cooperative K/V load: 4 kv-heads x 64 rows x 32 dims
#pragma unroll
    for (int it = 0; it < 8; it++) {
        int id = tid + 256 * it;              // 0..2047 float4 ids
        int kh = id >> 9;
        int j = (id >> 3) & 63;
        int d4 = id & 7;
        size_t gidx = (size_t)(bc * 64 + j) * 128 + kh * 32 + d4 * 4;
        *(float4*)&Ks[(kh * 64 + j) * 36 + d4 * 4] = *(const float4*)(K + gidx);
        *(float4*)&Vs[(kh * 64 + j) * 36 + d4 * 4] = *(const float4*)(V + gidx);
    }

    int h = wid;
    int kh = h >> 1;
    float* Sw = Wsall + h * ATT_WARP_F;
    const float scale = 0.17677669529663689f;  // 1/sqrt(32)

    // stage this head's Q (scaled) into the warp workspace
#pragma unroll
    for (int rr = 0; rr < 2; rr++) {
        int i = lane + 32 * rr;
        const float* qrow = Q + (size_t)(bc * 64 + i) * 256 + h * 32;
#pragma unroll
        for (int d4 = 0; d4 < 8; d4++) {
            float4 q = *(const float4*)(qrow + d4 * 4);
            q.x *= scale; q.y *= scale; q.z *= scale; q.w *= scale;
            *(float4*)&Sw[i * 68 + d4 * 4] = q;
        }
    }
    __syncthreads();

    // Q fragments (4 m-tiles x 4 k-tiles)
    unsigned aq[4][4][4];
#pragma unroll
    for (int mt = 0; mt < 4; mt++) {
        int r = 16 * mt + gid;
#pragma unroll
        for (int kt = 0; kt < 4; kt++) {
            aq[mt][kt][0] = f2tf(Sw[r * 68 + 8 * kt + ctid]);
            aq[mt][kt][1] = f2tf(Sw[(r + 8) * 68 + 8 * kt + ctid]);
            aq[mt][kt][2] = f2tf(Sw[r * 68 + 8 * kt + ctid + 4]);
            aq[mt][kt][3] = f2tf(Sw[(r + 8) * 68 + 8 * kt + ctid + 4]);
        }
    }
    __syncwarp();

    // S = Q @ K^T, stored into workspace (overwriting Q staging)
#pragma unroll
    for (int nt = 0; nt < 8; nt++) {
        float acc[4][4];
#pragma unroll
        for (int mt = 0; mt < 4; mt++)
#pragma unroll
            for (int j = 0; j < 4; j++) acc[mt][j] = 0.f;
#pragma unroll
        for (int kt = 0; kt < 4; kt++) {
            int jrow = kh * 64 + 8 * nt + gid;
            unsigned b0 = f2tf(Ks[jrow * 36 + 8 * kt + ctid]);
            unsigned b1 = f2tf(Ks[jrow * 36 + 8 * kt + ctid + 4]);
#pragma unroll
            for (int mt = 0; mt < 4; mt++)
                mma_tf32(acc[mt], aq[mt][kt][0], aq[mt][kt][1], aq[mt][kt][2], aq[mt][kt][3],
                         b0, b1);
        }
#pragma unroll
        for (int mt = 0; mt < 4; mt++) {
            int r = 16 * mt + gid, cc = 8 * nt + 2 * ctid;
            *(float2*)&Sw[r * 68 + cc] = make_float2(acc[mt][0], acc[mt][1]);
            *(float2*)&Sw[(r + 8) * 68 + cc] = make_float2(acc[mt][2], acc[mt][3]);
        }
    }
    __syncwarp();

    // softmax rows (unnormalized exp; store 1/rowsum at col 64)
#pragma unroll
    for (int rr = 0; rr < 2; rr++) {
        int i = lane + 32 * rr;
        float* row = &Sw[i * 68];
        float mx = -1e30f;
#pragma unroll
        for (int c4 = 0; c4 < 16; c4++) {
            float4 v = *(float4*)&row[c4 * 4];
            mx = fmaxf(mx, fmaxf(fmaxf(v.x, v.y), fmaxf(v.z, v.w)));
        }
        float sum = 0.f;
#pragma unroll
        for (int c4 = 0; c4 < 16; c4++) {
            float4 v = *(float4*)&row[c4 * 4];
            v.x = __expf(v.x - mx); v.y = __expf(v.y - mx);
            v.z = __expf(v.z - mx); v.w = __expf(v.w - mx);
            sum += v.x + v.y + v.z + v.w;
            *(float4*)&row[c4 * 4] = v;
        }
        row[64] = 1.f / sum;
    }
    __syncwarp();

    // O = P @ V
    float oacc[4][4][4];
#pragma unroll
    for (int mt = 0; mt < 4; mt++)
#pragma unroll
        for (int nt = 0; nt < 4; nt++)
#pragma unroll
            for (int j = 0; j < 4; j++) oacc[mt][nt][j] = 0.f;

#pragma unroll
    for (int kt = 0; kt < 8; kt++) {
        unsigned ap[4][4];
#pragma unroll
        for (int mt = 0; mt < 4; mt++) {
            int r = 16 * mt + gid;
            ap[mt][0] = f2tf(Sw[r * 68 + 8 * kt + ctid]);
            ap[mt][1] = f2tf(Sw[(r + 8) * 68 + 8 * kt + ctid]);
            ap[mt][2] = f2tf(Sw[r * 68 + 8 * kt + ctid + 4]);
            ap[mt][3] = f2tf(Sw[(r + 8) * 68 + 8 * kt + ctid + 4]);
        }
        unsigned bv[4][2];
#pragma unroll
        for (int nt = 0; nt < 4; nt++) {
            bv[nt][0] = f2tf(Vs[(kh * 64 + 8 * kt + ctid) * 36 + 8 * nt + gid]);
            bv[nt][1] = f2tf(Vs[(kh * 64 + 8 * kt + ctid + 4) * 36 + 8 * nt + gid]);
        }
#pragma unroll
        for (int mt = 0; mt < 4; mt++)
#pragma unroll
            for (int nt = 0; nt < 4; nt++)
                mma_tf32(oacc[mt][nt], ap[mt][0], ap[mt][1], ap[mt][2], ap[mt][3],
                         bv[nt][0], bv[nt][1]);
    }

    // write attention output, scaled by 1/rowsum
#pragma unroll
    for (int mt = 0; mt < 4; mt++) {
        int r0 = 16 * mt + gid;
        float rs0 = Sw[r0 * 68 + 64];
        float rs1 = Sw[(r0 + 8) * 68 + 64];
#pragma unroll
        for (int nt = 0; nt < 4; nt++) {
            int d = 8 * nt + 2 * ctid;
            float* o0 = AO + (size_t)(bc * 64 + r0) * 256 + h * 32 + d;
            *(float2*)o0 = make_float2(oacc[mt][nt][0] * rs0, oacc[mt][nt][1] * rs0);
            float* o1 = AO + (size_t)(bc * 64 + r0 + 8) * 256 + h * 32 + d;
            *(float2*)o1 = make_float2(oacc[mt][nt][2] * rs1, oacc[mt][nt][3] * rs1);
        }
    }
}

// ---------------------------------------------------------------------------
// Host launcher
// ---------------------------------------------------------------------------
extern "C" void kernel_launch(void* const* d_in, const int* in_sizes, int n_in,
                              void* d_out, int out_size) {
    const float* x_spec    = (const float*)d_in[0];
    const float* x_spat    = (const float*)d_in[1];
    const float* g_spec_q  = (const float*)d_in[2];
    const float* b_spec_q  = (const float*)d_in[3];
    const float* g_spec_kv = (const float*)d_in[4];
    const float* b_spec_kv = (const float*)d_in[5];
    const float* g_spat_q  = (const float*)d_in[6];
    const float* b_spat_q  = (const float*)d_in[7];
    const float* g_spat_kv = (const float*)d_in[8];
    const float* b_spat_kv = (const float*)d_in[9];
    const float* Wq_s2t = (const float*)d_in[10]; const float* bq_s2t = (const float*)d_in[11];
    const float* Wk_s2t = (const float*)d_in[12]; const float* bk_s2t = (const float*)d_in[13];
    const float* Wv_s2t = (const float*)d_in[14]; const float* bv_s2t = (const float*)d_in[15];
    const float* Wo_s2t = (const float*)d_in[16]; const float* bo_s2t = (const float*)d_in[17];
    const float* Wq_t2s = (const float*)d_in[18]; const float* bq_t2s = (const float*)d_in[19];
    const float* Wk_t2s = (const float*)d_in[20]; const float* bk_t2s = (const float*)d_in[21];
    const float* Wv_t2s = (const float*)d_in[22]; const float* bv_t2s = (const float*)d_in[23];
    const float* Wo_t2s = (const float*)d_in[24]; const float* bo_t2s = (const float*)d_in[25];
    const float* gate_spec = (const float*)d_in[26];
    const float* gate_spat = (const float*)d_in[27];
    float* out = (float*)d_out;

    float* buf = nullptr;
    cudaGetSymbolAddress((void**)&buf, g_buf);
    float* nA  = buf + OFF_NORMA;
    float* nB  = buf + OFF_NORMB;
    float* q0  = buf + OFF_Q;             float* q1 = q0 + (size_t)T_ROWS * 256;
    float* k0  = buf + OFF_K;             float* k1 = k0 + (size_t)T_ROWS * 128;
    float* v0  = buf + OFF_V;             float* v1 = v0 + (size_t)T_ROWS * 128;
    float* ao0 = buf + OFF_AO;            float* ao1 = ao0 + (size_t)T_ROWS * 256;
    float* wq0 = buf + OFF_WQ;            float* wq1 = wq0 + 65536;
    float* wk0 = buf + OFF_WK;            float* wk1 = wk0 + 32768;
    float* wv0 = buf + OFF_WV;            float* wv1 = wv0 + 32768;
    float* bq0 = buf + OFF_BQ;            float* bq1 = bq0 + 256;
    float* bk0 = buf + OFF_BK;            float* bk1 = bk0 + 128;
    float* bv0 = buf + OFF_BV;            float* bv1 = bv0 + 128;

    // --- weight prep (fold LN affine into projections) ---
    scale_w_kernel<<<256, 256>>>(Wq_s2t, g_spec_q, wq0, 256);
    scale_w_kernel<<<128, 256>>>(Wk_s2t, g_spat_kv, wk0, 128);
    scale_w_kernel<<<128, 256>>>(Wv_s2t, g_spat_kv, wv0, 128);
    scale_w_kernel<<<256, 256>>>(Wq_t2s, g_spat_q, wq1, 256);
    scale_w_kernel<<<128, 256>>>(Wk_t2s, g_spec_kv, wk1, 128);
    scale_w_kernel<<<128, 256>>>(Wv_t2s, g_spec_kv, wv1, 128);
    bias_fold_kernel<<<1, 256>>>(Wq_s2t, b_spec_q, bq_s2t, bq0, 256);
    bias_fold_kernel<<<1, 128>>>(Wk_s2t, b_spat_kv, bk_s2t, bk0, 128);
    bias_fold_kernel<<<1, 128>>>(Wv_s2t, b_spat_kv, bv_s2t, bv0, 128);
    bias_fold_kernel<<<1, 256>>>(Wq_t2s, b_spat_q, bq_t2s, bq1, 256);
    bias_fold_kernel<<<1, 128>>>(Wk_t2s, b_spec_kv, bk_t2s, bk1, 128);
    bias_fold_kernel<<<1, 128>>>(Wv_t2s, b_spec_kv, bv_t2s, bv1, 128);

    // --- layernorm (normalization only) ---
    ln_kernel<<<16384, 256>>>(x_spec, x_spat, nA, nB);

    // --- QKV projections ---
    // module 0 (s2t): Q from norm(spec), K/V from norm(spat)
    gemm_kernel<<<dim3(512, 4), 256>>>(nA, wq0, bq0, q0, 256, 0, nullptr, nullptr);
    gemm_kernel<<<dim3(512, 2), 256>>>(nB, wk0, bk0, k0, 128, 0, nullptr, nullptr);
    gemm_kernel<<<dim3(512, 2), 256>>>(nB, wv0, bv0, v0, 128, 0, nullptr, nullptr);
    // module 1 (t2s): Q from norm(spat), K/V from norm(spec)
    gemm_kernel<<<dim3(512, 4), 256>>>(nB, wq1, bq1, q1, 256, 0, nullptr, nullptr);
    gemm_kernel<<<dim3(512, 2), 256>>>(nA, wk1, bk1, k1, 128, 0, nullptr, nullptr);
    gemm_kernel<<<dim3(512, 2), 256>>>(nA, wv1, bv1, v1, 128, 0, nullptr, nullptr);

    // --- attention (both modules in one launch) ---
    cudaFuncSetAttribute(attn_kernel, cudaFuncAttributeMaxDynamicSharedMemorySize, ATT_SMEM_B);
    attn_kernel<<<dim3(1024, 2), 256, ATT_SMEM_B>>>(q0, k0, v0, ao0);

    // --- O-projection + gate + residual + transpose back ---
    gemm_kernel<<<dim3(512, 4), 256>>>(ao0, Wo_s2t, bo_s2t, out, 256, 1, x_spec, gate_spec);
    gemm_kernel<<<dim3(512, 4), 256>>>(ao1, Wo_t2s, bo_t2s, out + (size_t)T_ROWS * 256, 256, 1,
                                       x_spat, gate_spat);
}

// round 6
// speedup vs baseline: 1.4867x; 1.4867x over previous
#include <cuda_runtime.h>
#include <math.h>
#include <stdint.h>

// ---------------------------------------------------------------------------
// Problem constants
// ---------------------------------------------------------------------------
#define T_ROWS 65536      // B*C*S tokens (1024 * 64)

// scratch layout (float offsets)
#define OFF_NA    0UL          // 65536*256
#define OFF_NB    16777216UL
#define OFF_QKVA  33554432UL   // 65536*512  (q0 | k1 | v1)
#define OFF_QKVB  67108864UL   // 65536*512  (q1 | k0 | v0)
#define OFF_AO    100663296UL  // 2 * 65536*256
#define OFF_WA    134217728UL  // 512*256 transposed concat weights (A-side)
#define OFF_WB    134348800UL
#define OFF_WO0   134479872UL  // 256*256 transposed
#define OFF_WO1   134545408UL
#define OFF_BA    134610944UL  // 512
#define OFF_BB    134611456UL
#define BUF_TOTAL 134611968UL

__device__ float g_buf[BUF_TOTAL];

// ---------------------------------------------------------------------------
// tf32 helpers — round ONCE at the producer; consumers feed raw bits to mma.
// ---------------------------------------------------------------------------
__device__ __forceinline__ unsigned f2tf(float x) {
    unsigned r;
    asm("cvt.rna.tf32.f32 %0, %1;" : "=r"(r) : "f"(x));
    return r;
}
__device__ __forceinline__ float tfr(float x) {  // tf32-rounded value as float
    return __uint_as_float(f2tf(x));
}

__device__ __forceinline__ void mma_tf32(float* c,
                                         unsigned a0, unsigned a1, unsigned a2, unsigned a3,
                                         unsigned b0, unsigned b1) {
    asm("mma.sync.aligned.m16n8k8.row.col.f32.tf32.tf32.f32 "
        "{%0,%1,%2,%3},{%4,%5,%6,%7},{%8,%9},{%0,%1,%2,%3};"
        : "+f"(c[0]), "+f"(c[1]), "+f"(c[2]), "+f"(c[3])
        : "r"(a0), "r"(a1), "r"(a2), "r"(a3), "r"(b0), "r"(b1));
}

__device__ __forceinline__ void cpa16(float* dst, const float* src) {
    unsigned d = (unsigned)__cvta_generic_to_shared(dst);
    asm volatile("cp.async.ca.shared.global [%0], [%1], 16;" :: "r"(d), "l"(src));
}
#define CP_COMMIT() asm volatile("cp.async.commit_group;")

// ---------------------------------------------------------------------------
// Prep: build transposed, LN-scaled, tf32-rounded concat weight buffers.
// wcatA[n][d] (n<512, d<256):
//   n<256:   Wq_s2t[d][n]      * g_spec_q[d]
//   n<384:   Wk_t2s[d][n-256]  * g_spec_kv[d]
//   else:    Wv_t2s[d][n-384]  * g_spec_kv[d]
// wcatB: (Wq_t2s,g_spat_q) / (Wk_s2t,g_spat_kv) / (Wv_s2t,g_spat_kv)
// woT{0,1}[n][d] = Wo_{s2t,t2s}[d][n]  (rounded)
// ---------------------------------------------------------------------------
__global__ void prep_w_kernel(
    const float* __restrict__ Wq0, const float* __restrict__ Wk0, const float* __restrict__ Wv0,
    const float* __restrict__ Wq1, const float* __restrict__ Wk1, const float* __restrict__ Wv1,
    const float* __restrict__ Wo0, const float* __restrict__ Wo1,
    const float* __restrict__ g_spec_q, const float* __restrict__ g_spec_kv,
    const float* __restrict__ g_spat_q, const float* __restrict__ g_spat_kv,
    float* __restrict__ wA, float* __restrict__ wB,
    float* __restrict__ woT0, float* __restrict__ woT1) {
    int idx = blockIdx.x * blockDim.x + threadIdx.x;  // < 393216
    if (idx < 262144) {
        int half = idx >> 17;           // 0: wA, 1: wB
        int loc = idx & 131071;
        int n = loc >> 8, d = loc & 255;
        float v;
        if (half == 0) {
            if (n < 256)      v = Wq0[d * 256 + n]        * g_spec_q[d];
            else if (n < 384) v = Wk1[d * 128 + (n - 256)] * g_spec_kv[d];
            else              v = Wv1[d * 128 + (n - 384)] * g_spec_kv[d];
            wA[loc] = tfr(v);
        } else {
            if (n < 256)      v = Wq1[d * 256 + n]        * g_spat_q[d];
            else if (n < 384) v = Wk0[d * 128 + (n - 256)] * g_spat_kv[d];
            else              v = Wv0[d * 128 + (n - 384)] * g_spat_kv[d];
            wB[loc] = tfr(v);
        }
    } else {
        int loc = idx - 262144;         // < 131072
        int half = loc >> 16;
        int l2 = loc & 65535;
        int n = l2 >> 8, d = l2 & 255;
        if (half == 0) woT0[l2] = tfr(Wo0[d * 256 + n]);
        else           woT1[l2] = tfr(Wo1[d * 256 + n]);
    }
}

// Folded biases: bcat[n] = b_lin[n'] + sum_d b_ln[d] * W[d][n']
__global__ void prep_bias_kernel(
    const float* __restrict__ Wq0, const float* __restrict__ Wk0, const float* __restrict__ Wv0,
    const float* __restrict__ Wq1, const float* __restrict__ Wk1, const float* __restrict__ Wv1,
    const float* __restrict__ bq0, const float* __restrict__ bk0, const float* __restrict__ bv0,
    const float* __restrict__ bq1, const float* __restrict__ bk1, const float* __restrict__ bv1,
    const float* __restrict__ b_spec_q, const float* __restrict__ b_spec_kv,
    const float* __restrict__ b_spat_q, const float* __restrict__ b_spat_kv,
    float* __restrict__ bA, float* __restrict__ bB) {
    int idx = blockIdx.x * blockDim.x + threadIdx.x;  // < 1024
    if (idx >= 1024) return;
    int half = idx >> 9;   // 0: A-side, 1: B-side
    int n = idx & 511;
    const float* W; const float* bl; const float* bb; int nn; int N;
    if (half == 0) {
        if (n < 256)      { W = Wq0; bl = b_spec_q;  bb = bq0; nn = n;       N = 256; }
        else if (n < 384) { W = Wk1; bl = b_spec_kv; bb = bk1; nn = n - 256; N = 128; }
        else              { W = Wv1; bl = b_spec_kv; bb = bv1; nn = n - 384; N = 128; }
    } else {
        if (n < 256)      { W = Wq1; bl = b_spat_q;  bb = bq1; nn = n;       N = 256; }
        else if (n < 384) { W = Wk0; bl = b_spat_kv; bb = bk0; nn = n - 256; N = 128; }
        else              { W = Wv0; bl = b_spat_kv; bb = bv0; nn = n - 384; N = 128; }
    }
    float s = bb[nn];
    for (int d = 0; d < 256; d++) s += bl[d] * W[d * N + nn];
    if (half == 0) bA[n] = s; else bB[n] = s;
}

// ---------------------------------------------------------------------------
// LayerNorm (normalization only), writes tf32-rounded values.
// ---------------------------------------------------------------------------
__global__ void __launch_bounds__(256) ln_kernel(const float* __restrict__ x_spec,
                                                 const float* __restrict__ x_spat,
                                                 float* __restrict__ normA,
                                                 float* __restrict__ normB) {
    int gw = blockIdx.x * 8 + (threadIdx.x >> 5);
    int lane = threadIdx.x & 31;
    const float* src;
    float* dst;
    int r;
    if (gw < T_ROWS) { src = x_spec; dst = normA; r = gw; }
    else             { src = x_spat; dst = normB; r = gw - T_ROWS; }
    int bc = r >> 6, s = r & 63;
    int b = bc >> 7, c = bc & 127;
    const float* row = src + ((size_t)((b * 64 + s) * 128 + c)) * 256;
    float v[8];
    float sum = 0.f, sq = 0.f;
#pragma unroll
    for (int t = 0; t < 8; t++) {
        float x = row[lane + 32 * t];
        v[t] = x; sum += x; sq += x * x;
    }
#pragma unroll
    for (int o = 16; o > 0; o >>= 1) {
        sum += __shfl_xor_sync(0xffffffffu, sum, o);
        sq  += __shfl_xor_sync(0xffffffffu, sq, o);
    }
    float mu  = sum * (1.f / 256.f);
    float var = sq * (1.f / 256.f) - mu * mu;
    float rs  = rsqrtf(var + 1e-5f);
    float* orow = dst + (size_t)r * 256;
#pragma unroll
    for (int t = 0; t < 8; t++) orow[lane + 32 * t] = tfr((v[t] - mu) * rs);
}

// ---------------------------------------------------------------------------
// tf32 GEMM, cp.async double-buffered.
//   C[M=65536, NB] = A[M,256] @ Bt^T   (Bt stored [n][k], both tf32-rounded)
// mode 0: store tf32-rounded, row stride NS.
// mode 1: O-proj epilogue: out = x + sigmoid(gate)*(C+bias), transpose back.
// Tiles: BM=128, BN=128, BK=32; 8 warps (4m x 2n), warp tile 32x64.
// ---------------------------------------------------------------------------
#define GSTG 4608   // 128*36 floats per stage

__global__ void __launch_bounds__(256) gemm_kernel(
    const float* __restrict__ A, const float* __restrict__ Bt, const float* __restrict__ bias,
    float* __restrict__ out, int NS, int mode,
    const float* __restrict__ xres, const float* __restrict__ gate) {
    extern __shared__ float sm[];
    int tid = threadIdx.x;
    int wid = tid >> 5, lane = tid & 31;
    int gid = lane >> 2, ctid = lane & 3;
    int wm = (wid & 3) * 32;
    int wn = (wid >> 2) * 64;
    int rowBase = blockIdx.x * 128;
    int colBase = blockIdx.y * 128;

    float acc[2][8][4];
#pragma unroll
    for (int mt = 0; mt < 2; mt++)
#pragma unroll
        for (int nt = 0; nt < 8; nt++)
#pragma unroll
            for (int j = 0; j < 4; j++) acc[mt][nt][j] = 0.f;

    int ldr = tid >> 3, ldc = (tid & 7) * 4;  // 32 rows x 8 float4 per 256-thr pass

    // prefetch stage 0
    {
        float* As = sm;
        float* Bs = sm + 2 * GSTG;
#pragma unroll
        for (int i = 0; i < 4; i++) {
            int r = ldr + 32 * i;
            cpa16(&As[r * 36 + ldc], A + (size_t)(rowBase + r) * 256 + ldc);
            cpa16(&Bs[r * 36 + ldc], Bt + (size_t)(colBase + r) * 256 + ldc);
        }
        CP_COMMIT();
    }

    for (int it = 0; it < 8; it++) {
        if (it < 7) {
            int s = (it + 1) & 1;
            int k0 = (it + 1) * 32;
            float* As = sm + s * GSTG;
            float* Bs = sm + (2 + s) * GSTG;
#pragma unroll
            for (int i = 0; i < 4; i++) {
                int r = ldr + 32 * i;
                cpa16(&As[r * 36 + ldc], A + (size_t)(rowBase + r) * 256 + k0 + ldc);
                cpa16(&Bs[r * 36 + ldc], Bt + (size_t)(colBase + r) * 256 + k0 + ldc);
            }
            CP_COMMIT();
            asm volatile("cp.async.wait_group 1;");
        } else {
            asm volatile("cp.async.wait_group 0;");
        }
        __syncthreads();

        int s = it & 1;
        const float* As = sm + s * GSTG;
        const float* Bs = sm + (2 + s) * GSTG;
#pragma unroll
        for (int kt = 0; kt < 4; kt++) {
            int kk = 8 * kt + ctid;
            unsigned a[2][4];
#pragma unroll
            for (int mt = 0; mt < 2; mt++) {
                int r = wm + 16 * mt + gid;
                a[mt][0] = __float_as_uint(As[r * 36 + kk]);
                a[mt][1] = __float_as_uint(As[(r + 8) * 36 + kk]);
                a[mt][2] = __float_as_uint(As[r * 36 + kk + 4]);
                a[mt][3] = __float_as_uint(As[(r + 8) * 36 + kk + 4]);
            }
            unsigned b[8][2];
#pragma unroll
            for (int nt = 0; nt < 8; nt++) {
                int cc = wn + 8 * nt + gid;
                b[nt][0] = __float_as_uint(Bs[cc * 36 + kk]);
                b[nt][1] = __float_as_uint(Bs[cc * 36 + kk + 4]);
            }
#pragma unroll
            for (int mt = 0; mt < 2; mt++)
#pragma unroll
                for (int nt = 0; nt < 8; nt++)
                    mma_tf32(acc[mt][nt], a[mt][0], a[mt][1], a[mt][2], a[mt][3],
                             b[nt][0], b[nt][1]);
        }
        __syncthreads();
    }

    float gs = 0.f;
    if (mode == 1) gs = 1.f / (1.f + __expf(-gate[0]));

#pragma unroll
    for (int mt = 0; mt < 2; mt++) {
#pragma unroll
        for (int nt = 0; nt < 8; nt++) {
            int e = colBase + wn + 8 * nt + 2 * ctid;
            float b0 = bias[e], b1 = bias[e + 1];
            int r0 = rowBase + wm + 16 * mt + gid;
            float v00 = acc[mt][nt][0] + b0, v01 = acc[mt][nt][1] + b1;
            float v10 = acc[mt][nt][2] + b0, v11 = acc[mt][nt][3] + b1;
            if (mode == 0) {
                *(float2*)(out + (size_t)r0 * NS + e) = make_float2(tfr(v00), tfr(v01));
                *(float2*)(out + (size_t)(r0 + 8) * NS + e) = make_float2(tfr(v10), tfr(v11));
            } else {
#pragma unroll
                for (int rr = 0; rr < 2; rr++) {
                    int r = r0 + 8 * rr;
                    int bc = r >> 6, ss = r & 63;
                    int bb = bc >> 7, cc2 = bc & 127;
                    size_t idx = ((size_t)((bb * 64 + ss) * 128 + cc2)) * 256 + e;
                    float2 xv = *(const float2*)(xres + idx);
                    float va = (rr == 0) ? v00 : v10;
                    float vb = (rr == 0) ? v01 : v11;
                    *(float2*)(out + idx) = make_float2(xv.x + gs * va, xv.y + gs * vb);
                }
            }
        }
    }
}

// ---------------------------------------------------------------------------
// Attention: block = (bc, module), warp = head. GQA: head h -> kv head h/2.
// Q/K/V live in the fused QKV buffers (row stride 512):
//   module 0: Q = QKVA[:,0:256], K = QKVB[:,256:384], V = QKVB[:,384:512]
//   module 1: Q = QKVB[:,0:256], K = QKVA[:,256:384], V = QKVA[:,384:512]
// All tf32-rounded at producers -> no cvt here. Scale applied post-mma.
// ---------------------------------------------------------------------------
#define ATT_KS_F   (4 * 64 * 36)
#define ATT_WARP_F (64 * 68)
#define ATT_SMEM_F (2 * ATT_KS_F + 8 * ATT_WARP_F)
#define ATT_SMEM_B (ATT_SMEM_F * 4)

__global__ void __launch_bounds__(256) attn_kernel(const float* __restrict__ QKVA,
                                                   const float* __restrict__ QKVB,
                                                   float* __restrict__ AOb) {
    extern __shared__ float sm[];
    float* Ks = sm;
    float* Vs = sm + ATT_KS_F;
    float* Wsall = sm + 2 * ATT_KS_F;

    int m = blockIdx.y;
    int bc = blockIdx.x;
    const float* Q  = m ? QKVB : QKVA;
    const float* KV = m ? QKVA : QKVB;
    float* AO = AOb + (size_t)m * T_ROWS * 256;

    int tid = threadIdx.x, wid = tid >> 5, lane = tid & 31;
    int gid = lane >> 2, ctid = lane & 3;

    // cooperative K/V load: 4 kv-heads x 64 rows x 32 dims
#pragma unroll
    for (int it = 0; it < 8; it++) {
        int id = tid + 256 * it;
        int kh2 = id >> 9;
        int j = (id >> 3) & 63;
        int d4 = id & 7;
        size_t base = (size_t)(bc * 64 + j) * 512 + kh2 * 32 + d4 * 4;
        *(float4*)&Ks[(kh2 * 64 + j) * 36 + d4 * 4] = *(const float4*)(KV + base + 256);
        *(float4*)&Vs[(kh2 * 64 + j) * 36 + d4 * 4] = *(const float4*)(KV + base + 384);
    }

    int h = wid;
    int kh = h >> 1;
    float* Sw = Wsall + h * ATT_WARP_F;
    const float scale = 0.17677669529663689f;  // 1/sqrt(32)

    // stage this head's Q into the warp workspace (already rounded)
#pragma unroll
    for (int rr = 0; rr < 2; rr++) {
        int i = lane + 32 * rr;
        const float* qrow = Q + (size_t)(bc * 64 + i) * 512 + h * 32;
#pragma unroll
        for (int d4 = 0; d4 < 8; d4++)
            *(float4*)&Sw[i * 68 + d4 * 4] = *(const float4*)(qrow + d4 * 4);
    }
    __syncthreads();

    // Q fragments (4 m-tiles x 4 k-tiles)
    unsigned aq[4][4][4];
#pragma unroll
    for (int mt = 0; mt < 4; mt++) {
        int r = 16 * mt + gid;
#pragma unroll
        for (int kt = 0; kt < 4; kt++) {
            int kk = 8 * kt + ctid;
            aq[mt][kt][0] = __float_as_uint(Sw[r * 68 + kk]);
            aq[mt][kt][1] = __float_as_uint(Sw[(r + 8) * 68 + kk]);
            aq[mt][kt][2] = __float_as_uint(Sw[r * 68 + kk + 4]);
            aq[mt][kt][3] = __float_as_uint(Sw[(r + 8) * 68 + kk + 4]);
        }
    }
    __syncwarp();

    // S = Q @ K^T (scale applied at store)
#pragma unroll
    for (int nt = 0; nt < 8; nt++) {
        float acc[4][4];
#pragma unroll
        for (int mt = 0; mt < 4; mt++)
#pragma unroll
            for (int j = 0; j < 4; j++) acc[mt][j] = 0.f;
#pragma unroll
        for (int kt = 0; kt < 4; kt++) {
            int jrow = kh * 64 + 8 * nt + gid;
            int kk = 8 * kt + ctid;
            unsigned b0 = __float_as_uint(Ks[jrow * 36 + kk]);
            unsigned b1 = __float_as_uint(Ks[jrow * 36 + kk + 4]);
#pragma unroll
            for (int mt = 0; mt < 4; mt++)
                mma_tf32(acc[mt], aq[mt][kt][0], aq[mt][kt][1], aq[mt][kt][2], aq[mt][kt][3],
                         b0, b1);
        }
#pragma unroll
        for (int mt = 0; mt < 4; mt++) {
            int r = 16 * mt + gid, cc = 8 * nt + 2 * ctid;
            *(float2*)&Sw[r * 68 + cc] = make_float2(acc[mt][0] * scale, acc[mt][1] * scale);
            *(float2*)&Sw[(r + 8) * 68 + cc] = make_float2(acc[mt][2] * scale, acc[mt][3] * scale);
        }
    }
    __syncwarp();

    // softmax rows: unnormalized exp (tf32-rounded at store), 1/rowsum at col 64
#pragma unroll
    for (int rr = 0; rr < 2; rr++) {
        int i = lane + 32 * rr;
        float* row = &Sw[i * 68];
        float mx = -1e30f;
#pragma unroll
        for (int c4 = 0; c4 < 16; c4++) {
            float4 v = *(float4*)&row[c4 * 4];
            mx = fmaxf(mx, fmaxf(fmaxf(v.x, v.y), fmaxf(v.z, v.w)));
        }
        float sum = 0.f;
#pragma unroll
        for (int c4 = 0; c4 < 16; c4++) {
            float4 v = *(float4*)&row[c4 * 4];
            v.x = __expf(v.x - mx); v.y = __expf(v.y - mx);
            v.z = __expf(v.z - mx); v.w = __expf(v.w - mx);
            sum += v.x + v.y + v.z + v.w;
            v.x = tfr(v.x); v.y = tfr(v.y); v.z = tfr(v.z); v.w = tfr(v.w);
            *(float4*)&row[c4 * 4] = v;
        }
        row[64] = 1.f / sum;
    }
    __syncwarp();

    // O = P @ V
    float oacc[4][4][4];
#pragma unroll
    for (int mt = 0; mt < 4; mt++)
#pragma unroll
        for (int nt = 0; nt < 4; nt++)
#pragma unroll
            for (int j = 0; j < 4; j++) oacc[mt][nt][j] = 0.f;

#pragma unroll
    for (int kt = 0; kt < 8; kt++) {
        int kk = 8 * kt + ctid;
        unsigned ap[4][4];
#pragma unroll
        for (int mt = 0; mt < 4; mt++) {
            int r = 16 * mt + gid;
            ap[mt][0] = __float_as_uint(Sw[r * 68 + kk]);
            ap[mt][1] = __float_as_uint(Sw[(r + 8) * 68 + kk]);
            ap[mt][2] = __float_as_uint(Sw[r * 68 + kk + 4]);
            ap[mt][3] = __float_as_uint(Sw[(r + 8) * 68 + kk + 4]);
        }
        unsigned bv[4][2];
#pragma unroll
        for (int nt = 0; nt < 4; nt++) {
            bv[nt][0] = __float_as_uint(Vs[(kh * 64 + kk) * 36 + 8 * nt + gid]);
            bv[nt][1] = __float_as_uint(Vs[(kh * 64 + kk + 4) * 36 + 8 * nt + gid]);
        }
#pragma unroll
        for (int mt = 0; mt < 4; mt++)
#pragma unroll
            for (int nt = 0; nt < 4; nt++)
                mma_tf32(oacc[mt][nt], ap[mt][0], ap[mt][1], ap[mt][2], ap[mt][3],
                         bv[nt][0], bv[nt][1]);
    }

    // write attention output (tf32-rounded; feeds O-proj gemm), scaled by 1/rowsum
#pragma unroll
    for (int mt = 0; mt < 4; mt++) {
        int r0 = 16 * mt + gid;
        float rs0 = Sw[r0 * 68 + 64];
        float rs1 = Sw[(r0 + 8) * 68 + 64];
#pragma unroll
        for (int nt = 0; nt < 4; nt++) {
            int d = 8 * nt + 2 * ctid;
            float* o0 = AO + (size_t)(bc * 64 + r0) * 256 + h * 32 + d;
            *(float2*)o0 = make_float2(tfr(oacc[mt][nt][0] * rs0), tfr(oacc[mt][nt][1] * rs0));
            float* o1 = AO + (size_t)(bc * 64 + r0 + 8) * 256 + h * 32 + d;
            *(float2*)o1 = make_float2(tfr(oacc[mt][nt][2] * rs1), tfr(oacc[mt][nt][3] * rs1));
        }
    }
}

// ---------------------------------------------------------------------------
// Host launcher
// ---------------------------------------------------------------------------
extern "C" void kernel_launch(void* const* d_in, const int* in_sizes, int n_in,
                              void* d_out, int out_size) {
    const float* x_spec    = (const float*)d_in[0];
    const float* x_spat    = (const float*)d_in[1];
    const float* g_spec_q  = (const float*)d_in[2];
    const float* b_spec_q  = (const float*)d_in[3];
    const float* g_spec_kv = (const float*)d_in[4];
    const float* b_spec_kv = (const float*)d_in[5];
    const float* g_spat_q  = (const float*)d_in[6];
    const float* b_spat_q  = (const float*)d_in[7];
    const float* g_spat_kv = (const float*)d_in[8];
    const float* b_spat_kv = (const float*)d_in[9];
    const float* Wq_s2t = (const float*)d_in[10]; const float* bq_s2t = (const float*)d_in[11];
    const float* Wk_s2t = (const float*)d_in[12]; const float* bk_s2t = (const float*)d_in[13];
    const float* Wv_s2t = (const float*)d_in[14]; const float* bv_s2t = (const float*)d_in[15];
    const float* Wo_s2t = (const float*)d_in[16]; const float* bo_s2t = (const float*)d_in[17];
    const float* Wq_t2s = (const float*)d_in[18]; const float* bq_t2s = (const float*)d_in[19];
    const float* Wk_t2s = (const float*)d_in[20]; const float* bk_t2s = (const float*)d_in[21];
    const float* Wv_t2s = (const float*)d_in[22]; const float* bv_t2s = (const float*)d_in[23];
    const float* Wo_t2s = (const float*)d_in[24]; const float* bo_t2s = (const float*)d_in[25];
    const float* gate_spec = (const float*)d_in[26];
    const float* gate_spat = (const float*)d_in[27];
    float* out = (float*)d_out;

    float* buf = nullptr;
    cudaGetSymbolAddress((void**)&buf, g_buf);
    float* nA   = buf + OFF_NA;
    float* nB   = buf + OFF_NB;
    float* qkvA = buf + OFF_QKVA;
    float* qkvB = buf + OFF_QKVB;
    float* ao0  = buf + OFF_AO;   float* ao1 = ao0 + (size_t)T_ROWS * 256;
    float* wA   = buf + OFF_WA;
    float* wB   = buf + OFF_WB;
    float* woT0 = buf + OFF_WO0;
    float* woT1 = buf + OFF_WO1;
    float* bA   = buf + OFF_BA;
    float* bB   = buf + OFF_BB;

    // --- prep: scaled/transposed/rounded weights + folded biases ---
    prep_w_kernel<<<1536, 256>>>(Wq_s2t, Wk_s2t, Wv_s2t, Wq_t2s, Wk_t2s, Wv_t2s,
                                 Wo_s2t, Wo_t2s,
                                 g_spec_q, g_spec_kv, g_spat_q, g_spat_kv,
                                 wA, wB, woT0, woT1);
    prep_bias_kernel<<<4, 256>>>(Wq_s2t, Wk_s2t, Wv_s2t, Wq_t2s, Wk_t2s, Wv_t2s,
                                 bq_s2t, bk_s2t, bv_s2t, bq_t2s, bk_t2s, bv_t2s,
                                 b_spec_q, b_spec_kv, b_spat_q, b_spat_kv, bA, bB);

    // --- layernorm ---
    ln_kernel<<<16384, 256>>>(x_spec, x_spat, nA, nB);

    // --- fused QKV projections (one gemm per A operand) ---
    const int GEMM_SMEM = 4 * GSTG * 4;  // 73728 B
    cudaFuncSetAttribute(gemm_kernel, cudaFuncAttributeMaxDynamicSharedMemorySize, GEMM_SMEM);
    gemm_kernel<<<dim3(512, 4), 256, GEMM_SMEM>>>(nA, wA, bA, qkvA, 512, 0, nullptr, nullptr);
    gemm_kernel<<<dim3(512, 4), 256, GEMM_SMEM>>>(nB, wB, bB, qkvB, 512, 0, nullptr, nullptr);

    // --- attention (both modules) ---
    cudaFuncSetAttribute(attn_kernel, cudaFuncAttributeMaxDynamicSharedMemorySize, ATT_SMEM_B);
    attn_kernel<<<dim3(1024, 2), 256, ATT_SMEM_B>>>(qkvA, qkvB, ao0);

    // --- O-projection + gate + residual + transpose back ---
    gemm_kernel<<<dim3(512, 2), 256, GEMM_SMEM>>>(ao0, woT0, bo_s2t, out, 256, 1,
                                                  x_spec, gate_spec);
    gemm_kernel<<<dim3(512, 2), 256, GEMM_SMEM>>>(ao1, woT1, bo_t2s,
                                                  out + (size_t)T_ROWS * 256, 256, 1,
                                                  x_spat, gate_spat);
}